// round 7
// baseline (speedup 1.0000x reference)
#include <cuda_runtime.h>

#define NN 50000
#define NE 1600000
#define F 32
#define NWORDS (NN * F)
#define SCAN_T 1024
#define CHUNK ((NN + SCAN_T - 1) / SCAN_T)   // 49

// ---------------- scratch (device globals; no allocation allowed) ----------
__device__ __align__(16) float g_deg[NN];
__device__ __align__(16) float g_dinv[NN];
__device__ __align__(16) int   g_count[NN];
__device__ __align__(16) int   g_rowptr[NN + 1];
__device__ __align__(16) int   g_cursor[NN];
__device__ __align__(16) int2  g_csr[NE];       // (src, __float_as_int(norm)) sorted by dst
__device__ __align__(16) float g_U[5][NWORDS];  // U[0] doubles as layer-1 output h1
__device__ __align__(16) float g_Whead[F];
__device__ float g_bhead[1];

// ---------------- setup kernels --------------------------------------------
__global__ void zero_kernel() {
    int i = blockIdx.x * blockDim.x + threadIdx.x;
    if (i < NN) { g_deg[i] = 0.f; g_count[i] = 0; }
}

// one pass over edges: deg[src] += w  and  count[dst]++
__global__ void deg_hist_kernel(const int* __restrict__ src, const int* __restrict__ dst,
                                const float* __restrict__ w) {
    int e = blockIdx.x * blockDim.x + threadIdx.x;
    if (e < NE) {
        atomicAdd(&g_deg[src[e]], w[e]);
        atomicAdd(&g_count[dst[e]], 1);
    }
}

__global__ void dinv_kernel() {
    int i = blockIdx.x * blockDim.x + threadIdx.x;
    if (i < NN) {
        float d = g_deg[i];
        g_dinv[i] = d > 0.f ? rsqrtf(fmaxf(d, 1e-12f)) : 0.f;
    }
}

// single-block exclusive scan of g_count -> g_rowptr (+ cursor init)
__global__ void scan_kernel() {
    __shared__ int ssum[SCAN_T];
    int t = threadIdx.x;
    int base = t * CHUNK;
    int s = 0;
#pragma unroll
    for (int i = 0; i < CHUNK; i++) {
        int idx = base + i;
        if (idx < NN) s += g_count[idx];
    }
    ssum[t] = s;
    __syncthreads();
    // Hillis-Steele inclusive scan
    for (int off = 1; off < SCAN_T; off <<= 1) {
        int v = ssum[t];
        int add = (t >= off) ? ssum[t - off] : 0;
        __syncthreads();
        ssum[t] = v + add;
        __syncthreads();
    }
    int run = (t > 0) ? ssum[t - 1] : 0;
#pragma unroll
    for (int i = 0; i < CHUNK; i++) {
        int idx = base + i;
        if (idx < NN) {
            g_rowptr[idx] = run;
            g_cursor[idx] = run;
            run += g_count[idx];
        }
    }
    if (t == SCAN_T - 1) g_rowptr[NN] = NE;
}

// scatter edges into CSR slots, computing norm inline
__global__ void fill_kernel(const int* __restrict__ src, const int* __restrict__ dst,
                            const float* __restrict__ w) {
    int e = blockIdx.x * blockDim.x + threadIdx.x;
    if (e >= NE) return;
    int s = src[e];
    int d = dst[e];
    float nm = -g_dinv[s] * w[e] * g_dinv[d];
    int pos = atomicAdd(&g_cursor[d], 1);
    g_csr[pos] = make_int2(s, __float_as_int(nm));
}

// ---------------- sparse propagation (CSR, atomic-free) --------------------
// warp per destination node, lane = feature; register accumulation
__global__ void prop_csr_kernel(const float* __restrict__ xin, float* __restrict__ yout) {
    int warp = (blockIdx.x * blockDim.x + threadIdx.x) >> 5;
    int lane = threadIdx.x & 31;
    if (warp >= NN) return;
    int beg = g_rowptr[warp];
    int end = g_rowptr[warp + 1];
    float acc = 0.f;
    for (int eb = beg; eb < end; eb += 32) {
        int rem = end - eb;
        int2 rec = (lane < rem) ? g_csr[eb + lane] : make_int2(0, 0);
        int cnt = rem < 32 ? rem : 32;
        int i = 0;
        for (; i + 4 <= cnt; i += 4) {
            int s0 = __shfl_sync(0xffffffffu, rec.x, i);
            int s1 = __shfl_sync(0xffffffffu, rec.x, i + 1);
            int s2 = __shfl_sync(0xffffffffu, rec.x, i + 2);
            int s3 = __shfl_sync(0xffffffffu, rec.x, i + 3);
            float n0 = __int_as_float(__shfl_sync(0xffffffffu, rec.y, i));
            float n1 = __int_as_float(__shfl_sync(0xffffffffu, rec.y, i + 1));
            float n2 = __int_as_float(__shfl_sync(0xffffffffu, rec.y, i + 2));
            float n3 = __int_as_float(__shfl_sync(0xffffffffu, rec.y, i + 3));
            float v0 = __ldg(xin + (size_t)s0 * F + lane);
            float v1 = __ldg(xin + (size_t)s1 * F + lane);
            float v2 = __ldg(xin + (size_t)s2 * F + lane);
            float v3 = __ldg(xin + (size_t)s3 * F + lane);
            acc += n0 * v0;
            acc += n1 * v1;
            acc += n2 * v2;
            acc += n3 * v3;
        }
        for (; i < cnt; i++) {
            int s0 = __shfl_sync(0xffffffffu, rec.x, i);
            float n0 = __int_as_float(__shfl_sync(0xffffffffu, rec.y, i));
            acc += n0 * __ldg(xin + (size_t)s0 * F + lane);
        }
    }
    yout[(size_t)warp * F + lane] = acc;
}

// ---------------- head composition: 4 linears -> single [32] matvec --------
__global__ void head_kernel(const float* __restrict__ hw1, const float* __restrict__ hb1,
                            const float* __restrict__ hw2, const float* __restrict__ hb2,
                            const float* __restrict__ hw3, const float* __restrict__ hb3,
                            const float* __restrict__ hw4, const float* __restrict__ hb4) {
    int r = threadIdx.x;  // 32 threads
    if (r >= 32) return;
    float w12[8];
#pragma unroll
    for (int j = 0; j < 8; j++) {
        float s = 0.f;
#pragma unroll
        for (int i = 0; i < 16; i++) s += hw1[r * 16 + i] * hw2[i * 8 + j];
        w12[j] = s;
    }
    float w123[4];
#pragma unroll
    for (int j = 0; j < 4; j++) {
        float s = 0.f;
#pragma unroll
        for (int i = 0; i < 8; i++) s += w12[i] * hw3[i * 4 + j];
        w123[j] = s;
    }
    float wf = 0.f;
#pragma unroll
    for (int i = 0; i < 4; i++) wf += w123[i] * hw4[i];
    g_Whead[r] = wf;

    if (r == 0) {
        float b2[8];
        for (int j = 0; j < 8; j++) {
            float s = hb2[j];
            for (int i = 0; i < 16; i++) s += hb1[i] * hw2[i * 8 + j];
            b2[j] = s;
        }
        float b3[4];
        for (int j = 0; j < 4; j++) {
            float s = hb3[j];
            for (int i = 0; i < 8; i++) s += b2[i] * hw3[i * 4 + j];
            b3[j] = s;
        }
        float b4 = hb4[0];
        for (int i = 0; i < 4; i++) b4 += b3[i] * hw4[i];
        g_bhead[0] = b4;
    }
}

// ---------------- fused gate kernel (4 nodes per warp) ----------------------
// Per node n:  cx_g[o] = bias_g[o] + sum_j sum_i U_j[n][i] * W'_{g,j}[i][o]
// gates {i, c, o}; forget gate & Wh dead (H=C=0).
// I=sig(cxI); Cn=I*tanh(cxC); O=sig(cxO+wc2*Cn); h=relu(O*tanh(Cn))
// Layer1: h -> out[n][:]. Layer2: out[n] = h.Whead + bhead (folded 4-linear head)
__global__ void gate_kernel(const float* __restrict__ u0,
                            const float* __restrict__ Wx,   // [4][5][32][32]
                            const float* __restrict__ bx,   // [4][32]
                            const float* __restrict__ bh,   // [4][32]
                            const float* __restrict__ wc,   // [3][32]
                            const float* __restrict__ bb,   // [4][32]
                            float* __restrict__ out,
                            int is_layer2) {
    extern __shared__ float smem[];
    float* sW = smem;              // [3][5*32][32] = 15360 floats
    float* sBias = smem + 15360;   // [3][32]
    float* sWc2 = sBias + 96;      // [32]
    float* sWhead = sWc2 + 32;     // [32]

    const int gmap[3] = {0, 2, 3};

    // load + Chebyshev->power-basis weight transform
    for (int idx = threadIdx.x; idx < 3 * 32 * 32; idx += blockDim.x) {
        int gi = idx >> 10;
        int i = (idx >> 5) & 31;
        int o = idx & 31;
        int g = gmap[gi];
        const float* base = Wx + (size_t)g * 5120 + i * 32 + o;  // stride 1024 per k
        float w0 = base[0];
        float w1 = base[1024];
        float w2 = base[2048];
        float w3 = base[3072];
        float w4 = base[4096];
        float* sw = sW + gi * 5120 + i * 32 + o;
        sw[0 * 1024] = w0 - w2 + w4;
        sw[1 * 1024] = w1 - 3.f * w3;
        sw[2 * 1024] = 2.f * w2 - 8.f * w4;
        sw[3 * 1024] = 4.f * w3;
        sw[4 * 1024] = 8.f * w4;
    }
    for (int idx = threadIdx.x; idx < 32; idx += blockDim.x) {
        sBias[idx]      = bx[0 * 32 + idx] + bh[0 * 32 + idx] + bb[0 * 32 + idx];
        sBias[32 + idx] = bx[2 * 32 + idx] + bh[2 * 32 + idx] + bb[2 * 32 + idx];
        sBias[64 + idx] = bx[3 * 32 + idx] + bh[3 * 32 + idx] + bb[3 * 32 + idx];
        sWc2[idx] = wc[2 * 32 + idx];
        sWhead[idx] = g_Whead[idx];
    }
    __syncthreads();

    int lane = threadIdx.x & 31;
    int warp = (blockIdx.x * blockDim.x + threadIdx.x) >> 5;
    int nwarps = (gridDim.x * blockDim.x) >> 5;
    float bhead = g_bhead[0];
    float biasI = sBias[lane];
    float biasC = sBias[32 + lane];
    float biasO = sBias[64 + lane];
    float wc2 = sWc2[lane];
    float whead = sWhead[lane];

    // NN % 4 == 0: each warp iteration handles 4 consecutive nodes
    for (int nb = warp * 4; nb < NN; nb += nwarps * 4) {
        float ua[5], ub[5], uc[5], ud[5];
#pragma unroll
        for (int j = 0; j < 5; j++) {
            const float* Uj = (j == 0) ? u0 : &g_U[j][0];
            ua[j] = Uj[(size_t)(nb + 0) * F + lane];
            ub[j] = Uj[(size_t)(nb + 1) * F + lane];
            uc[j] = Uj[(size_t)(nb + 2) * F + lane];
            ud[j] = Uj[(size_t)(nb + 3) * F + lane];
        }
        float aI = biasI, aC = biasC, aO = biasO;
        float bI = biasI, bC = biasC, bO = biasO;
        float cI = biasI, cC = biasC, cO = biasO;
        float dI = biasI, dC = biasC, dO = biasO;
#pragma unroll
        for (int j = 0; j < 5; j++) {
#pragma unroll 8
            for (int i = 0; i < 32; i++) {
                int row = j * 1024 + i * 32 + lane;
                float wI = sW[row];
                float wC = sW[5120 + row];
                float wO = sW[10240 + row];
                float va = __shfl_sync(0xffffffffu, ua[j], i);
                float vb = __shfl_sync(0xffffffffu, ub[j], i);
                float vc = __shfl_sync(0xffffffffu, uc[j], i);
                float vd = __shfl_sync(0xffffffffu, ud[j], i);
                aI += va * wI; aC += va * wC; aO += va * wO;
                bI += vb * wI; bC += vb * wC; bO += vb * wO;
                cI += vc * wI; cC += vc * wC; cO += vc * wO;
                dI += vd * wI; dC += vd * wC; dO += vd * wO;
            }
        }
        float accsI[4] = {aI, bI, cI, dI};
        float accsC[4] = {aC, bC, cC, dC};
        float accsO[4] = {aO, bO, cO, dO};
#pragma unroll
        for (int t = 0; t < 4; t++) {
            float I = 1.f / (1.f + __expf(-accsI[t]));
            float Cn = I * tanhf(accsC[t]);
            float O = 1.f / (1.f + __expf(-(accsO[t] + wc2 * Cn)));
            float h = fmaxf(O * tanhf(Cn), 0.f);
            if (!is_layer2) {
                out[(size_t)(nb + t) * F + lane] = h;
            } else {
                float v = h * whead;
#pragma unroll
                for (int off = 16; off; off >>= 1) v += __shfl_xor_sync(0xffffffffu, v, off);
                if (lane == 0) out[nb + t] = v + bhead;
            }
        }
    }
}

// ---------------- launcher ---------------------------------------------------
extern "C" void kernel_launch(void* const* d_in, const int* in_sizes, int n_in,
                              void* d_out, int out_size) {
    const float* x   = (const float*)d_in[0];
    const int* eidx  = (const int*)d_in[1];
    const float* ew  = (const float*)d_in[2];
    const float* l1_Wx = (const float*)d_in[3];
    const float* l1_bx = (const float*)d_in[4];
    const float* l1_bh = (const float*)d_in[6];
    const float* l1_wc = (const float*)d_in[7];
    const float* l1_b  = (const float*)d_in[8];
    const float* l2_Wx = (const float*)d_in[9];
    const float* l2_bx = (const float*)d_in[10];
    const float* l2_bh = (const float*)d_in[12];
    const float* l2_wc = (const float*)d_in[13];
    const float* l2_b  = (const float*)d_in[14];
    const float* hw1 = (const float*)d_in[15];
    const float* hb1 = (const float*)d_in[16];
    const float* hw2 = (const float*)d_in[17];
    const float* hb2 = (const float*)d_in[18];
    const float* hw3 = (const float*)d_in[19];
    const float* hb3 = (const float*)d_in[20];
    const float* hw4 = (const float*)d_in[21];
    const float* hb4 = (const float*)d_in[22];
    float* out = (float*)d_out;

    const int* src = eidx;
    const int* dst = eidx + NE;

    float* U0;
    float* U1;
    float* U2;
    float* U3;
    float* U4;
    {
        void* p;
        cudaGetSymbolAddress(&p, g_U);
        U0 = (float*)p;
        U1 = U0 + NWORDS;
        U2 = U0 + 2 * NWORDS;
        U3 = U0 + 3 * NWORDS;
        U4 = U0 + 4 * NWORDS;
    }

    const int T = 256;
    const int gridN = (NN + T - 1) / T;
    const int gridE = (NE + T - 1) / T;
    const int gridP = (NN * 32 + T - 1) / T;   // warp per node
    const int gateBlocks = 148 * 3;
    const int gateSmem = (15360 + 96 + 32 + 32) * (int)sizeof(float);

    cudaFuncSetAttribute(gate_kernel, cudaFuncAttributeMaxDynamicSharedMemorySize, gateSmem);

    // graph preprocessing: degrees + histogram -> dinv -> rowptr -> CSR fill
    zero_kernel<<<gridN, T>>>();
    deg_hist_kernel<<<gridE, T>>>(src, dst, ew);
    dinv_kernel<<<gridN, T>>>();
    scan_kernel<<<1, SCAN_T>>>();
    fill_kernel<<<gridE, T>>>(src, dst, ew);
    head_kernel<<<1, 32>>>(hw1, hb1, hw2, hb2, hw3, hb3, hw4, hb4);

    // ---- layer 1: U_k = L^k x ----
    prop_csr_kernel<<<gridP, T>>>(x, U1);
    prop_csr_kernel<<<gridP, T>>>(U1, U2);
    prop_csr_kernel<<<gridP, T>>>(U2, U3);
    prop_csr_kernel<<<gridP, T>>>(U3, U4);
    gate_kernel<<<gateBlocks, T, gateSmem>>>(x, l1_Wx, l1_bx, l1_bh, l1_wc, l1_b,
                                             U0, 0);

    // ---- layer 2: U_k = L^k h1 (h1 lives in U0) ----
    prop_csr_kernel<<<gridP, T>>>(U0, U1);
    prop_csr_kernel<<<gridP, T>>>(U1, U2);
    prop_csr_kernel<<<gridP, T>>>(U2, U3);
    prop_csr_kernel<<<gridP, T>>>(U3, U4);
    gate_kernel<<<gateBlocks, T, gateSmem>>>(U0, l2_Wx, l2_bx, l2_bh, l2_wc, l2_b,
                                             out, 1);
}

// round 8
// speedup vs baseline: 1.1381x; 1.1381x over previous
#include <cuda_runtime.h>
#include <cuda_fp16.h>

#define NN 50000
#define NE 1600000
#define F 32
#define NWORDS (NN * F)
#define NB 196            // ceil(NN/256)

// ---------------- scratch (device globals; no allocation allowed) ----------
__device__ __align__(16) float    g_deg[NN];
__device__ __align__(16) float    g_dinv[NN];
__device__ __align__(16) int      g_count[NN];
__device__ __align__(16) int      g_bsum[NB];
__device__ __align__(16) int      g_boff[NB];
__device__ __align__(16) int      g_rowptr[NN + 1];
__device__ __align__(16) int      g_cursor[NN];
__device__ __align__(16) unsigned g_csrp[NE];        // packed: src(u16) | normfp16<<16, sorted by dst
__device__ __align__(16) __half   g_Xh[NWORDS];      // fp16 copy of x
__device__ __align__(16) __half   g_Uh[5][NWORDS];   // U[0] = layer-1 output h1
__device__ __align__(16) float    g_Whead[F];
__device__ float g_bhead[1];

// ---------------- setup kernels --------------------------------------------
__global__ void zero_kernel() {
    int i = blockIdx.x * blockDim.x + threadIdx.x;
    if (i < NN) { g_deg[i] = 0.f; g_count[i] = 0; }
}

// one pass over edges: deg[src] += w  and  count[dst]++
__global__ void deg_hist_kernel(const int* __restrict__ src, const int* __restrict__ dst,
                                const float* __restrict__ w) {
    int e = blockIdx.x * blockDim.x + threadIdx.x;
    if (e < NE) {
        atomicAdd(&g_deg[src[e]], w[e]);
        atomicAdd(&g_count[dst[e]], 1);
    }
}

__global__ void dinv_kernel() {
    int i = blockIdx.x * blockDim.x + threadIdx.x;
    if (i < NN) {
        float d = g_deg[i];
        g_dinv[i] = d > 0.f ? rsqrtf(fmaxf(d, 1e-12f)) : 0.f;
    }
}

__global__ void x2h_kernel(const float* __restrict__ x) {
    int i = blockIdx.x * blockDim.x + threadIdx.x;
    if (i < NWORDS) g_Xh[i] = __float2half(x[i]);
}

// -------- coalesced 3-stage scan of g_count -> g_rowptr / g_cursor ---------
__global__ void blocksum_kernel() {
    __shared__ int s[256];
    int idx = blockIdx.x * 256 + threadIdx.x;
    s[threadIdx.x] = (idx < NN) ? g_count[idx] : 0;
    __syncthreads();
    for (int off = 128; off; off >>= 1) {
        if (threadIdx.x < off) s[threadIdx.x] += s[threadIdx.x + off];
        __syncthreads();
    }
    if (threadIdx.x == 0) g_bsum[blockIdx.x] = s[0];
}

__global__ void bscan_kernel() {
    __shared__ int s[256];
    int t = threadIdx.x;
    s[t] = (t < NB) ? g_bsum[t] : 0;
    __syncthreads();
    for (int off = 1; off < 256; off <<= 1) {
        int v = s[t];
        int add = (t >= off) ? s[t - off] : 0;
        __syncthreads();
        s[t] = v + add;
        __syncthreads();
    }
    if (t < NB) g_boff[t] = (t > 0) ? s[t - 1] : 0;
}

__global__ void rowptr_kernel() {
    __shared__ int s[256];
    int t = threadIdx.x;
    int idx = blockIdx.x * 256 + t;
    int c = (idx < NN) ? g_count[idx] : 0;
    s[t] = c;
    __syncthreads();
    for (int off = 1; off < 256; off <<= 1) {
        int v = s[t];
        int add = (t >= off) ? s[t - off] : 0;
        __syncthreads();
        s[t] = v + add;
        __syncthreads();
    }
    int excl = s[t] - c + g_boff[blockIdx.x];
    if (idx < NN) {
        g_rowptr[idx] = excl;
        g_cursor[idx] = excl;
    }
    if (idx == NN - 1) g_rowptr[NN] = NE;
}

// scatter edges into CSR slots, packing (src u16, norm fp16) into one word
__global__ void fill_kernel(const int* __restrict__ src, const int* __restrict__ dst,
                            const float* __restrict__ w) {
    int e = blockIdx.x * blockDim.x + threadIdx.x;
    if (e >= NE) return;
    int s = src[e];
    int d = dst[e];
    float nm = -g_dinv[s] * w[e] * g_dinv[d];
    int pos = atomicAdd(&g_cursor[d], 1);
    unsigned nb = (unsigned)__half_as_ushort(__float2half(nm));
    g_csrp[pos] = (unsigned)s | (nb << 16);
}

// ---------------- sparse propagation (CSR, atomic-free, fp16) --------------
// warp per destination node, lane = feature; fp32 register accumulation
__global__ void prop_csr_kernel(const __half* __restrict__ xin, __half* __restrict__ yout) {
    int warp = (blockIdx.x * blockDim.x + threadIdx.x) >> 5;
    int lane = threadIdx.x & 31;
    if (warp >= NN) return;
    int beg = g_rowptr[warp];
    int end = g_rowptr[warp + 1];
    float acc = 0.f;
    for (int eb = beg; eb < end; eb += 32) {
        int rem = end - eb;
        unsigned rec = (lane < rem) ? g_csrp[eb + lane] : 0u;
        int cnt = rem < 32 ? rem : 32;
        int i = 0;
        for (; i + 4 <= cnt; i += 4) {
            unsigned r0 = __shfl_sync(0xffffffffu, rec, i);
            unsigned r1 = __shfl_sync(0xffffffffu, rec, i + 1);
            unsigned r2 = __shfl_sync(0xffffffffu, rec, i + 2);
            unsigned r3 = __shfl_sync(0xffffffffu, rec, i + 3);
            float v0 = __half2float(__ldg(xin + (r0 & 0xFFFFu) * F + lane));
            float v1 = __half2float(__ldg(xin + (r1 & 0xFFFFu) * F + lane));
            float v2 = __half2float(__ldg(xin + (r2 & 0xFFFFu) * F + lane));
            float v3 = __half2float(__ldg(xin + (r3 & 0xFFFFu) * F + lane));
            acc += __half2float(__ushort_as_half((unsigned short)(r0 >> 16))) * v0;
            acc += __half2float(__ushort_as_half((unsigned short)(r1 >> 16))) * v1;
            acc += __half2float(__ushort_as_half((unsigned short)(r2 >> 16))) * v2;
            acc += __half2float(__ushort_as_half((unsigned short)(r3 >> 16))) * v3;
        }
        for (; i < cnt; i++) {
            unsigned r0 = __shfl_sync(0xffffffffu, rec, i);
            float v0 = __half2float(__ldg(xin + (r0 & 0xFFFFu) * F + lane));
            acc += __half2float(__ushort_as_half((unsigned short)(r0 >> 16))) * v0;
        }
    }
    yout[(size_t)warp * F + lane] = __float2half(acc);
}

// ---------------- head composition: 4 linears -> single [32] matvec --------
__global__ void head_kernel(const float* __restrict__ hw1, const float* __restrict__ hb1,
                            const float* __restrict__ hw2, const float* __restrict__ hb2,
                            const float* __restrict__ hw3, const float* __restrict__ hb3,
                            const float* __restrict__ hw4, const float* __restrict__ hb4) {
    int r = threadIdx.x;  // 32 threads
    if (r >= 32) return;
    float w12[8];
#pragma unroll
    for (int j = 0; j < 8; j++) {
        float s = 0.f;
#pragma unroll
        for (int i = 0; i < 16; i++) s += hw1[r * 16 + i] * hw2[i * 8 + j];
        w12[j] = s;
    }
    float w123[4];
#pragma unroll
    for (int j = 0; j < 4; j++) {
        float s = 0.f;
#pragma unroll
        for (int i = 0; i < 8; i++) s += w12[i] * hw3[i * 4 + j];
        w123[j] = s;
    }
    float wf = 0.f;
#pragma unroll
    for (int i = 0; i < 4; i++) wf += w123[i] * hw4[i];
    g_Whead[r] = wf;

    if (r == 0) {
        float b2[8];
        for (int j = 0; j < 8; j++) {
            float s = hb2[j];
            for (int i = 0; i < 16; i++) s += hb1[i] * hw2[i * 8 + j];
            b2[j] = s;
        }
        float b3[4];
        for (int j = 0; j < 4; j++) {
            float s = hb3[j];
            for (int i = 0; i < 8; i++) s += b2[i] * hw3[i * 4 + j];
            b3[j] = s;
        }
        float b4 = hb4[0];
        for (int i = 0; i < 4; i++) b4 += b3[i] * hw4[i];
        g_bhead[0] = b4;
    }
}

// ---------------- fused gate kernel (4 nodes per warp) ----------------------
// Per node n:  cx_g[o] = bias_g[o] + sum_j sum_i U_j[n][i] * W'_{g,j}[i][o]
// gates {i, c, o}; forget gate & Wh dead (H=C=0).
// I=sig(cxI); Cn=I*tanh(cxC); O=sig(cxO+wc2*Cn); h=relu(O*tanh(Cn))
// Layer1: h -> outh[n][:] (fp16). Layer2: outf[n] = h.Whead + bhead
__global__ void gate_kernel(const __half* __restrict__ u0,
                            const float* __restrict__ Wx,   // [4][5][32][32]
                            const float* __restrict__ bx,   // [4][32]
                            const float* __restrict__ bh,   // [4][32]
                            const float* __restrict__ wc,   // [3][32]
                            const float* __restrict__ bb,   // [4][32]
                            __half* __restrict__ outh,
                            float* __restrict__ outf,
                            int is_layer2) {
    extern __shared__ float smem[];
    float* sW = smem;              // [3][5*32][32] = 15360 floats
    float* sBias = smem + 15360;   // [3][32]
    float* sWc2 = sBias + 96;      // [32]
    float* sWhead = sWc2 + 32;     // [32]

    const int gmap[3] = {0, 2, 3};

    // load + Chebyshev->power-basis weight transform
    for (int idx = threadIdx.x; idx < 3 * 32 * 32; idx += blockDim.x) {
        int gi = idx >> 10;
        int i = (idx >> 5) & 31;
        int o = idx & 31;
        int g = gmap[gi];
        const float* base = Wx + (size_t)g * 5120 + i * 32 + o;  // stride 1024 per k
        float w0 = base[0];
        float w1 = base[1024];
        float w2 = base[2048];
        float w3 = base[3072];
        float w4 = base[4096];
        float* sw = sW + gi * 5120 + i * 32 + o;
        sw[0 * 1024] = w0 - w2 + w4;
        sw[1 * 1024] = w1 - 3.f * w3;
        sw[2 * 1024] = 2.f * w2 - 8.f * w4;
        sw[3 * 1024] = 4.f * w3;
        sw[4 * 1024] = 8.f * w4;
    }
    for (int idx = threadIdx.x; idx < 32; idx += blockDim.x) {
        sBias[idx]      = bx[0 * 32 + idx] + bh[0 * 32 + idx] + bb[0 * 32 + idx];
        sBias[32 + idx] = bx[2 * 32 + idx] + bh[2 * 32 + idx] + bb[2 * 32 + idx];
        sBias[64 + idx] = bx[3 * 32 + idx] + bh[3 * 32 + idx] + bb[3 * 32 + idx];
        sWc2[idx] = wc[2 * 32 + idx];
        sWhead[idx] = g_Whead[idx];
    }
    __syncthreads();

    int lane = threadIdx.x & 31;
    int warp = (blockIdx.x * blockDim.x + threadIdx.x) >> 5;
    int nwarps = (gridDim.x * blockDim.x) >> 5;
    float bhead = g_bhead[0];
    float biasI = sBias[lane];
    float biasC = sBias[32 + lane];
    float biasO = sBias[64 + lane];
    float wc2 = sWc2[lane];
    float whead = sWhead[lane];

    // NN % 4 == 0: each warp iteration handles 4 consecutive nodes
    for (int nb = warp * 4; nb < NN; nb += nwarps * 4) {
        float ua[5], ub[5], uc[5], ud[5];
#pragma unroll
        for (int j = 0; j < 5; j++) {
            const __half* Uj = (j == 0) ? u0 : &g_Uh[j][0];
            ua[j] = __half2float(Uj[(size_t)(nb + 0) * F + lane]);
            ub[j] = __half2float(Uj[(size_t)(nb + 1) * F + lane]);
            uc[j] = __half2float(Uj[(size_t)(nb + 2) * F + lane]);
            ud[j] = __half2float(Uj[(size_t)(nb + 3) * F + lane]);
        }
        float aI = biasI, aC = biasC, aO = biasO;
        float bI = biasI, bC = biasC, bO = biasO;
        float cI = biasI, cC = biasC, cO = biasO;
        float dI = biasI, dC = biasC, dO = biasO;
#pragma unroll
        for (int j = 0; j < 5; j++) {
#pragma unroll 8
            for (int i = 0; i < 32; i++) {
                int row = j * 1024 + i * 32 + lane;
                float wI = sW[row];
                float wC = sW[5120 + row];
                float wO = sW[10240 + row];
                float va = __shfl_sync(0xffffffffu, ua[j], i);
                float vb = __shfl_sync(0xffffffffu, ub[j], i);
                float vc = __shfl_sync(0xffffffffu, uc[j], i);
                float vd = __shfl_sync(0xffffffffu, ud[j], i);
                aI += va * wI; aC += va * wC; aO += va * wO;
                bI += vb * wI; bC += vb * wC; bO += vb * wO;
                cI += vc * wI; cC += vc * wC; cO += vc * wO;
                dI += vd * wI; dC += vd * wC; dO += vd * wO;
            }
        }
        float accsI[4] = {aI, bI, cI, dI};
        float accsC[4] = {aC, bC, cC, dC};
        float accsO[4] = {aO, bO, cO, dO};
#pragma unroll
        for (int t = 0; t < 4; t++) {
            float I = 1.f / (1.f + __expf(-accsI[t]));
            float Cn = I * tanhf(accsC[t]);
            float O = 1.f / (1.f + __expf(-(accsO[t] + wc2 * Cn)));
            float h = fmaxf(O * tanhf(Cn), 0.f);
            if (!is_layer2) {
                outh[(size_t)(nb + t) * F + lane] = __float2half(h);
            } else {
                float v = h * whead;
#pragma unroll
                for (int off = 16; off; off >>= 1) v += __shfl_xor_sync(0xffffffffu, v, off);
                if (lane == 0) outf[nb + t] = v + bhead;
            }
        }
    }
}

// ---------------- launcher ---------------------------------------------------
extern "C" void kernel_launch(void* const* d_in, const int* in_sizes, int n_in,
                              void* d_out, int out_size) {
    const float* x   = (const float*)d_in[0];
    const int* eidx  = (const int*)d_in[1];
    const float* ew  = (const float*)d_in[2];
    const float* l1_Wx = (const float*)d_in[3];
    const float* l1_bx = (const float*)d_in[4];
    const float* l1_bh = (const float*)d_in[6];
    const float* l1_wc = (const float*)d_in[7];
    const float* l1_b  = (const float*)d_in[8];
    const float* l2_Wx = (const float*)d_in[9];
    const float* l2_bx = (const float*)d_in[10];
    const float* l2_bh = (const float*)d_in[12];
    const float* l2_wc = (const float*)d_in[13];
    const float* l2_b  = (const float*)d_in[14];
    const float* hw1 = (const float*)d_in[15];
    const float* hb1 = (const float*)d_in[16];
    const float* hw2 = (const float*)d_in[17];
    const float* hb2 = (const float*)d_in[18];
    const float* hw3 = (const float*)d_in[19];
    const float* hb3 = (const float*)d_in[20];
    const float* hw4 = (const float*)d_in[21];
    const float* hb4 = (const float*)d_in[22];
    float* out = (float*)d_out;

    const int* src = eidx;
    const int* dst = eidx + NE;

    __half* Xh;
    __half* U0;
    __half* U1;
    __half* U2;
    __half* U3;
    __half* U4;
    {
        void* p;
        cudaGetSymbolAddress(&p, g_Uh);
        U0 = (__half*)p;
        U1 = U0 + NWORDS;
        U2 = U0 + 2 * NWORDS;
        U3 = U0 + 3 * NWORDS;
        U4 = U0 + 4 * NWORDS;
        cudaGetSymbolAddress(&p, g_Xh);
        Xh = (__half*)p;
    }

    const int T = 256;
    const int gridN = (NN + T - 1) / T;
    const int gridE = (NE + T - 1) / T;
    const int gridW = (NWORDS + T - 1) / T;
    const int gridP = (NN * 32 + T - 1) / T;   // warp per node
    const int gateBlocks = 148 * 3;
    const int gateSmem = (15360 + 96 + 32 + 32) * (int)sizeof(float);

    cudaFuncSetAttribute(gate_kernel, cudaFuncAttributeMaxDynamicSharedMemorySize, gateSmem);

    // graph preprocessing: degrees + histogram -> dinv -> rowptr (3-stage scan) -> CSR fill
    zero_kernel<<<gridN, T>>>();
    deg_hist_kernel<<<gridE, T>>>(src, dst, ew);
    dinv_kernel<<<gridN, T>>>();
    blocksum_kernel<<<NB, 256>>>();
    bscan_kernel<<<1, 256>>>();
    rowptr_kernel<<<NB, 256>>>();
    fill_kernel<<<gridE, T>>>(src, dst, ew);
    x2h_kernel<<<gridW, T>>>(x);
    head_kernel<<<1, 32>>>(hw1, hb1, hw2, hb2, hw3, hb3, hw4, hb4);

    // ---- layer 1: U_k = L^k x ----
    prop_csr_kernel<<<gridP, T>>>(Xh, U1);
    prop_csr_kernel<<<gridP, T>>>(U1, U2);
    prop_csr_kernel<<<gridP, T>>>(U2, U3);
    prop_csr_kernel<<<gridP, T>>>(U3, U4);
    gate_kernel<<<gateBlocks, T, gateSmem>>>(Xh, l1_Wx, l1_bx, l1_bh, l1_wc, l1_b,
                                             U0, (float*)nullptr, 0);

    // ---- layer 2: U_k = L^k h1 (h1 lives in U0) ----
    prop_csr_kernel<<<gridP, T>>>(U0, U1);
    prop_csr_kernel<<<gridP, T>>>(U1, U2);
    prop_csr_kernel<<<gridP, T>>>(U2, U3);
    prop_csr_kernel<<<gridP, T>>>(U3, U4);
    gate_kernel<<<gateBlocks, T, gateSmem>>>(U0, l2_Wx, l2_bx, l2_bh, l2_wc, l2_b,
                                             (__half*)nullptr, out, 1);
}

// round 9
// speedup vs baseline: 1.3395x; 1.1770x over previous
#include <cuda_runtime.h>
#include <cuda_fp16.h>

#define NN 50000
#define NE 1600000
#define F 32
#define NWORDS (NN * F)
#define NB 196            // ceil(NN/256)

// ---------------- scratch (device globals; no allocation allowed) ----------
__device__ __align__(16) float    g_deg[NN];
__device__ __align__(16) float    g_dinv[NN];
__device__ __align__(16) int      g_count[NN];
__device__ __align__(16) int      g_bsum[NB];
__device__ __align__(16) int      g_boff[NB];
__device__ __align__(16) int      g_rowptr[NN + 1];
__device__ __align__(16) int      g_cursor[NN];
__device__ __align__(16) unsigned g_csrp[NE];        // packed: src(u16) | normfp16<<16, sorted by dst
__device__ __align__(16) __half   g_Xh[NWORDS];      // fp16 copy of x
__device__ __align__(16) __half   g_Uh[5][NWORDS];   // U[0] = layer-1 output h1
__device__ __align__(16) float    g_Whead[F];
__device__ float g_bhead[1];

// ---------------- f32x2 packed helpers --------------------------------------
__device__ __forceinline__ unsigned long long pack2(float a, float b) {
    unsigned long long r;
    asm("mov.b64 %0, {%1, %2};" : "=l"(r) : "f"(a), "f"(b));
    return r;
}
__device__ __forceinline__ void ffma2(unsigned long long& d, unsigned long long a,
                                      unsigned long long b) {
    asm("fma.rn.f32x2 %0, %1, %2, %0;" : "+l"(d) : "l"(a), "l"(b));
}
__device__ __forceinline__ float2 unpack2(unsigned long long p) {
    float2 f;
    asm("mov.b64 {%0, %1}, %2;" : "=f"(f.x), "=f"(f.y) : "l"(p));
    return f;
}

// ---------------- setup kernels --------------------------------------------
__global__ void zero_kernel() {
    int i = blockIdx.x * blockDim.x + threadIdx.x;
    if (i < NN) { g_deg[i] = 0.f; g_count[i] = 0; }
}

// one pass over edges: deg[src] += w  and  count[dst]++
__global__ void deg_hist_kernel(const int* __restrict__ src, const int* __restrict__ dst,
                                const float* __restrict__ w) {
    int e = blockIdx.x * blockDim.x + threadIdx.x;
    if (e < NE) {
        atomicAdd(&g_deg[src[e]], w[e]);
        atomicAdd(&g_count[dst[e]], 1);
    }
}

__global__ void dinv_kernel() {
    int i = blockIdx.x * blockDim.x + threadIdx.x;
    if (i < NN) {
        float d = g_deg[i];
        g_dinv[i] = d > 0.f ? rsqrtf(fmaxf(d, 1e-12f)) : 0.f;
    }
}

__global__ void x2h_kernel(const float* __restrict__ x) {
    int i = blockIdx.x * blockDim.x + threadIdx.x;
    if (i < NWORDS) g_Xh[i] = __float2half(x[i]);
}

// -------- coalesced 3-stage scan of g_count -> g_rowptr / g_cursor ---------
__global__ void blocksum_kernel() {
    __shared__ int s[256];
    int idx = blockIdx.x * 256 + threadIdx.x;
    s[threadIdx.x] = (idx < NN) ? g_count[idx] : 0;
    __syncthreads();
    for (int off = 128; off; off >>= 1) {
        if (threadIdx.x < off) s[threadIdx.x] += s[threadIdx.x + off];
        __syncthreads();
    }
    if (threadIdx.x == 0) g_bsum[blockIdx.x] = s[0];
}

__global__ void bscan_kernel() {
    __shared__ int s[256];
    int t = threadIdx.x;
    s[t] = (t < NB) ? g_bsum[t] : 0;
    __syncthreads();
    for (int off = 1; off < 256; off <<= 1) {
        int v = s[t];
        int add = (t >= off) ? s[t - off] : 0;
        __syncthreads();
        s[t] = v + add;
        __syncthreads();
    }
    if (t < NB) g_boff[t] = (t > 0) ? s[t - 1] : 0;
}

__global__ void rowptr_kernel() {
    __shared__ int s[256];
    int t = threadIdx.x;
    int idx = blockIdx.x * 256 + t;
    int c = (idx < NN) ? g_count[idx] : 0;
    s[t] = c;
    __syncthreads();
    for (int off = 1; off < 256; off <<= 1) {
        int v = s[t];
        int add = (t >= off) ? s[t - off] : 0;
        __syncthreads();
        s[t] = v + add;
        __syncthreads();
    }
    int excl = s[t] - c + g_boff[blockIdx.x];
    if (idx < NN) {
        g_rowptr[idx] = excl;
        g_cursor[idx] = excl;
    }
    if (idx == NN - 1) g_rowptr[NN] = NE;
}

// scatter edges into CSR slots, packing (src u16, norm fp16) into one word
__global__ void fill_kernel(const int* __restrict__ src, const int* __restrict__ dst,
                            const float* __restrict__ w) {
    int e = blockIdx.x * blockDim.x + threadIdx.x;
    if (e >= NE) return;
    int s = src[e];
    int d = dst[e];
    float nm = -g_dinv[s] * w[e] * g_dinv[d];
    int pos = atomicAdd(&g_cursor[d], 1);
    unsigned nb = (unsigned)__half_as_ushort(__float2half(nm));
    g_csrp[pos] = (unsigned)s | (nb << 16);
}

// ---------------- sparse propagation (CSR, half2, 2 edges / warp instr) ----
// Each warp owns TWO consecutive dst nodes; half-warp h handles node 2w+h.
// Lane = half*16 + hl; hl indexes half2 feature pairs (16 x half2 = 32 feats).
// One LDG.64 gathers two edges' 64B rows (one per half). Invalid slots carry
// rec=0 => norm=+0 => zero contribution (branch-free ragged tails).
#define PROP_BODY(i)                                                            \
    {                                                                           \
        unsigned r = __shfl_sync(0xffffffffu, rec, srcbase + (i));              \
        float nm = __half2float(__ushort_as_half((unsigned short)(r >> 16)));   \
        __half2 v = __ldg(xin2 + (size_t)(r & 0xFFFFu) * 16 + hl);              \
        float2 vf = __half22float2(v);                                          \
        accx = fmaf(nm, vf.x, accx);                                            \
        accy = fmaf(nm, vf.y, accy);                                            \
    }

__global__ void prop_csr_kernel(const __half2* __restrict__ xin2,
                                __half2* __restrict__ yout2) {
    int gwarp = (blockIdx.x * blockDim.x + threadIdx.x) >> 5;
    int lane = threadIdx.x & 31;
    int half = lane >> 4;
    int hl = lane & 15;
    int node = gwarp * 2 + half;
    if (node >= NN) return;   // NN even: whole warp exits together
    int beg = g_rowptr[node];
    int deg = g_rowptr[node + 1] - beg;
    int maxdeg = max(deg, __shfl_xor_sync(0xffffffffu, deg, 16));
    int srcbase = lane & 16;
    float accx = 0.f, accy = 0.f;
    for (int off = 0; off < maxdeg; off += 16) {
        int rem = deg - off;
        unsigned rec = (hl < rem) ? g_csrp[beg + off + hl] : 0u;
        int mc = maxdeg - off;
        if (mc >= 16) {
#pragma unroll
            for (int i = 0; i < 16; i++) PROP_BODY(i)
        } else {
            for (int i = 0; i < mc; i++) PROP_BODY(i)
        }
    }
    yout2[(size_t)node * 16 + hl] = __floats2half2_rn(accx, accy);
}

// ---------------- head composition: 4 linears -> single [32] matvec --------
__global__ void head_kernel(const float* __restrict__ hw1, const float* __restrict__ hb1,
                            const float* __restrict__ hw2, const float* __restrict__ hb2,
                            const float* __restrict__ hw3, const float* __restrict__ hb3,
                            const float* __restrict__ hw4, const float* __restrict__ hb4) {
    int r = threadIdx.x;  // 32 threads
    if (r >= 32) return;
    float w12[8];
#pragma unroll
    for (int j = 0; j < 8; j++) {
        float s = 0.f;
#pragma unroll
        for (int i = 0; i < 16; i++) s += hw1[r * 16 + i] * hw2[i * 8 + j];
        w12[j] = s;
    }
    float w123[4];
#pragma unroll
    for (int j = 0; j < 4; j++) {
        float s = 0.f;
#pragma unroll
        for (int i = 0; i < 8; i++) s += w12[i] * hw3[i * 4 + j];
        w123[j] = s;
    }
    float wf = 0.f;
#pragma unroll
    for (int i = 0; i < 4; i++) wf += w123[i] * hw4[i];
    g_Whead[r] = wf;

    if (r == 0) {
        float b2[8];
        for (int j = 0; j < 8; j++) {
            float s = hb2[j];
            for (int i = 0; i < 16; i++) s += hb1[i] * hw2[i * 8 + j];
            b2[j] = s;
        }
        float b3[4];
        for (int j = 0; j < 4; j++) {
            float s = hb3[j];
            for (int i = 0; i < 8; i++) s += b2[i] * hw3[i * 4 + j];
            b3[j] = s;
        }
        float b4 = hb4[0];
        for (int i = 0; i < 4; i++) b4 += b3[i] * hw4[i];
        g_bhead[0] = b4;
    }
}

// ---------------- fused gate kernel (4 nodes per warp, FFMA2) ---------------
// Per node n:  cx_g[o] = bias_g[o] + sum_j sum_i U_j[n][i] * W'_{g,j}[i][o]
// gates {i, c, o}; forget gate & Wh dead (H=C=0).
// Node pairs (a,b) and (c,d) are packed into f32x2 accumulators; fma.rn.f32x2
// halves FFMA-pipe pressure with bitwise-identical per-component rounding.
__global__ void gate_kernel(const __half* __restrict__ u0,
                            const float* __restrict__ Wx,   // [4][5][32][32]
                            const float* __restrict__ bx,   // [4][32]
                            const float* __restrict__ bh,   // [4][32]
                            const float* __restrict__ wc,   // [3][32]
                            const float* __restrict__ bb,   // [4][32]
                            __half* __restrict__ outh,
                            float* __restrict__ outf,
                            int is_layer2) {
    extern __shared__ float smem[];
    float* sW = smem;              // [3][5*32][32] = 15360 floats
    float* sBias = smem + 15360;   // [3][32]
    float* sWc2 = sBias + 96;      // [32]
    float* sWhead = sWc2 + 32;     // [32]

    const int gmap[3] = {0, 2, 3};

    // load + Chebyshev->power-basis weight transform
    for (int idx = threadIdx.x; idx < 3 * 32 * 32; idx += blockDim.x) {
        int gi = idx >> 10;
        int i = (idx >> 5) & 31;
        int o = idx & 31;
        int g = gmap[gi];
        const float* base = Wx + (size_t)g * 5120 + i * 32 + o;  // stride 1024 per k
        float w0 = base[0];
        float w1 = base[1024];
        float w2 = base[2048];
        float w3 = base[3072];
        float w4 = base[4096];
        float* sw = sW + gi * 5120 + i * 32 + o;
        sw[0 * 1024] = w0 - w2 + w4;
        sw[1 * 1024] = w1 - 3.f * w3;
        sw[2 * 1024] = 2.f * w2 - 8.f * w4;
        sw[3 * 1024] = 4.f * w3;
        sw[4 * 1024] = 8.f * w4;
    }
    for (int idx = threadIdx.x; idx < 32; idx += blockDim.x) {
        sBias[idx]      = bx[0 * 32 + idx] + bh[0 * 32 + idx] + bb[0 * 32 + idx];
        sBias[32 + idx] = bx[2 * 32 + idx] + bh[2 * 32 + idx] + bb[2 * 32 + idx];
        sBias[64 + idx] = bx[3 * 32 + idx] + bh[3 * 32 + idx] + bb[3 * 32 + idx];
        sWc2[idx] = wc[2 * 32 + idx];
        sWhead[idx] = g_Whead[idx];
    }
    __syncthreads();

    int lane = threadIdx.x & 31;
    int warp = (blockIdx.x * blockDim.x + threadIdx.x) >> 5;
    int nwarps = (gridDim.x * blockDim.x) >> 5;
    float bhead = g_bhead[0];
    float biasI = sBias[lane];
    float biasC = sBias[32 + lane];
    float biasO = sBias[64 + lane];
    float wc2 = sWc2[lane];
    float whead = sWhead[lane];

    // NN % 4 == 0: each warp iteration handles 4 consecutive nodes
    for (int nb = warp * 4; nb < NN; nb += nwarps * 4) {
        float ua[5], ub[5], uc[5], ud[5];
#pragma unroll
        for (int j = 0; j < 5; j++) {
            const __half* Uj = (j == 0) ? u0 : &g_Uh[j][0];
            ua[j] = __half2float(Uj[(size_t)(nb + 0) * F + lane]);
            ub[j] = __half2float(Uj[(size_t)(nb + 1) * F + lane]);
            uc[j] = __half2float(Uj[(size_t)(nb + 2) * F + lane]);
            ud[j] = __half2float(Uj[(size_t)(nb + 3) * F + lane]);
        }
        unsigned long long accI_ab = pack2(biasI, biasI), accI_cd = pack2(biasI, biasI);
        unsigned long long accC_ab = pack2(biasC, biasC), accC_cd = pack2(biasC, biasC);
        unsigned long long accO_ab = pack2(biasO, biasO), accO_cd = pack2(biasO, biasO);
#pragma unroll
        for (int j = 0; j < 5; j++) {
#pragma unroll 8
            for (int i = 0; i < 32; i++) {
                int row = j * 1024 + i * 32 + lane;
                float wI = sW[row];
                float wC = sW[5120 + row];
                float wO = sW[10240 + row];
                float va = __shfl_sync(0xffffffffu, ua[j], i);
                float vb = __shfl_sync(0xffffffffu, ub[j], i);
                float vc = __shfl_sync(0xffffffffu, uc[j], i);
                float vd = __shfl_sync(0xffffffffu, ud[j], i);
                unsigned long long pab = pack2(va, vb);
                unsigned long long pcd = pack2(vc, vd);
                unsigned long long wI2 = pack2(wI, wI);
                unsigned long long wC2 = pack2(wC, wC);
                unsigned long long wO2 = pack2(wO, wO);
                ffma2(accI_ab, pab, wI2);
                ffma2(accI_cd, pcd, wI2);
                ffma2(accC_ab, pab, wC2);
                ffma2(accC_cd, pcd, wC2);
                ffma2(accO_ab, pab, wO2);
                ffma2(accO_cd, pcd, wO2);
            }
        }
        float2 iab = unpack2(accI_ab), icd = unpack2(accI_cd);
        float2 cab = unpack2(accC_ab), ccd = unpack2(accC_cd);
        float2 oab = unpack2(accO_ab), ocd = unpack2(accO_cd);
        float accsI[4] = {iab.x, iab.y, icd.x, icd.y};
        float accsC[4] = {cab.x, cab.y, ccd.x, ccd.y};
        float accsO[4] = {oab.x, oab.y, ocd.x, ocd.y};
#pragma unroll
        for (int t = 0; t < 4; t++) {
            float I = 1.f / (1.f + __expf(-accsI[t]));
            float Cn = I * tanhf(accsC[t]);
            float O = 1.f / (1.f + __expf(-(accsO[t] + wc2 * Cn)));
            float h = fmaxf(O * tanhf(Cn), 0.f);
            if (!is_layer2) {
                outh[(size_t)(nb + t) * F + lane] = __float2half(h);
            } else {
                float v = h * whead;
#pragma unroll
                for (int off = 16; off; off >>= 1) v += __shfl_xor_sync(0xffffffffu, v, off);
                if (lane == 0) outf[nb + t] = v + bhead;
            }
        }
    }
}

// ---------------- launcher ---------------------------------------------------
extern "C" void kernel_launch(void* const* d_in, const int* in_sizes, int n_in,
                              void* d_out, int out_size) {
    const float* x   = (const float*)d_in[0];
    const int* eidx  = (const int*)d_in[1];
    const float* ew  = (const float*)d_in[2];
    const float* l1_Wx = (const float*)d_in[3];
    const float* l1_bx = (const float*)d_in[4];
    const float* l1_bh = (const float*)d_in[6];
    const float* l1_wc = (const float*)d_in[7];
    const float* l1_b  = (const float*)d_in[8];
    const float* l2_Wx = (const float*)d_in[9];
    const float* l2_bx = (const float*)d_in[10];
    const float* l2_bh = (const float*)d_in[12];
    const float* l2_wc = (const float*)d_in[13];
    const float* l2_b  = (const float*)d_in[14];
    const float* hw1 = (const float*)d_in[15];
    const float* hb1 = (const float*)d_in[16];
    const float* hw2 = (const float*)d_in[17];
    const float* hb2 = (const float*)d_in[18];
    const float* hw3 = (const float*)d_in[19];
    const float* hb3 = (const float*)d_in[20];
    const float* hw4 = (const float*)d_in[21];
    const float* hb4 = (const float*)d_in[22];
    float* out = (float*)d_out;

    const int* src = eidx;
    const int* dst = eidx + NE;

    __half* Xh;
    __half* U0;
    __half* U1;
    __half* U2;
    __half* U3;
    __half* U4;
    {
        void* p;
        cudaGetSymbolAddress(&p, g_Uh);
        U0 = (__half*)p;
        U1 = U0 + NWORDS;
        U2 = U0 + 2 * NWORDS;
        U3 = U0 + 3 * NWORDS;
        U4 = U0 + 4 * NWORDS;
        cudaGetSymbolAddress(&p, g_Xh);
        Xh = (__half*)p;
    }

    const int T = 256;
    const int gridN = (NN + T - 1) / T;
    const int gridE = (NE + T - 1) / T;
    const int gridW = (NWORDS + T - 1) / T;
    const int gridP = ((NN / 2) * 32 + T - 1) / T;   // warp per 2 nodes
    const int gateBlocks = 148 * 3;
    const int gateSmem = (15360 + 96 + 32 + 32) * (int)sizeof(float);

    cudaFuncSetAttribute(gate_kernel, cudaFuncAttributeMaxDynamicSharedMemorySize, gateSmem);

    // graph preprocessing: degrees + histogram -> dinv -> rowptr (3-stage scan) -> CSR fill
    zero_kernel<<<gridN, T>>>();
    deg_hist_kernel<<<gridE, T>>>(src, dst, ew);
    dinv_kernel<<<gridN, T>>>();
    blocksum_kernel<<<NB, 256>>>();
    bscan_kernel<<<1, 256>>>();
    rowptr_kernel<<<NB, 256>>>();
    fill_kernel<<<gridE, T>>>(src, dst, ew);
    x2h_kernel<<<gridW, T>>>(x);
    head_kernel<<<1, 32>>>(hw1, hb1, hw2, hb2, hw3, hb3, hw4, hb4);

    // ---- layer 1: U_k = L^k x ----
    prop_csr_kernel<<<gridP, T>>>((const __half2*)Xh, (__half2*)U1);
    prop_csr_kernel<<<gridP, T>>>((const __half2*)U1, (__half2*)U2);
    prop_csr_kernel<<<gridP, T>>>((const __half2*)U2, (__half2*)U3);
    prop_csr_kernel<<<gridP, T>>>((const __half2*)U3, (__half2*)U4);
    gate_kernel<<<gateBlocks, T, gateSmem>>>(Xh, l1_Wx, l1_bx, l1_bh, l1_wc, l1_b,
                                             U0, (float*)nullptr, 0);

    // ---- layer 2: U_k = L^k h1 (h1 lives in U0) ----
    prop_csr_kernel<<<gridP, T>>>((const __half2*)U0, (__half2*)U1);
    prop_csr_kernel<<<gridP, T>>>((const __half2*)U1, (__half2*)U2);
    prop_csr_kernel<<<gridP, T>>>((const __half2*)U2, (__half2*)U3);
    prop_csr_kernel<<<gridP, T>>>((const __half2*)U3, (__half2*)U4);
    gate_kernel<<<gateBlocks, T, gateSmem>>>(U0, l2_Wx, l2_bx, l2_bh, l2_wc, l2_b,
                                             (__half*)nullptr, out, 1);
}